// round 16
// baseline (speedup 1.0000x reference)
#include <cuda_runtime.h>
#include <cuda_bf16.h>
#include <math.h>

#define BATCH   2
#define NSEQ    2048
#define HEADS   8
#define DHEAD   64
#define DIMM    512
#define BHDIM   16
#define MROWS   4096
#define QROWS   32768
#define TVALS   1025
#define PLD     1028
#define SCALE_F 0.125f

typedef unsigned long long u64;
typedef unsigned int u32;

// ---------------- device scratch ---------------------------------------------
__device__ __nv_bfloat16 g_xhi[MROWS * DIMM];         // [m][k]
__device__ __nv_bfloat16 g_xlo[MROWS * DIMM];
__device__ __nv_bfloat16 g_Wthi[1536 * DIMM];         // [c][k]
__device__ __nv_bfloat16 g_Wtlo[1536 * DIMM];
__device__ __nv_bfloat16 g_WoThi[DIMM * DIMM];        // [c][k]
__device__ __nv_bfloat16 g_WoTlo[DIMM * DIMM];
__device__ __nv_bfloat16 g_relhi[1152 * DHEAD];       // [t][d] zero-padded
__device__ __nv_bfloat16 g_rello[1152 * DHEAD];
__device__ __nv_bfloat16 g_Qhi[QROWS * DHEAD];        // [bh][n][d] scaled
__device__ __nv_bfloat16 g_Qlo[QROWS * DHEAD];
__device__ __nv_bfloat16 g_Khi[QROWS * DHEAD];        // [bh][n][d]
__device__ __nv_bfloat16 g_Klo[QROWS * DHEAD];
__device__ __nv_bfloat16 g_Vhi[QROWS * DHEAD];        // [bh][d][n]
__device__ __nv_bfloat16 g_Vlo[QROWS * DHEAD];
__device__ __nv_bfloat16 g_Ohi[MROWS * DIMM];         // [m][h*d]
__device__ __nv_bfloat16 g_Olo[MROWS * DIMM];
__device__ float g_P [(size_t)QROWS * PLD];

// ---------------- bf16 split helpers -------------------------------------------
__device__ __forceinline__ void bfsplit2(float f0, float f1, u32& hi, u32& lo) {
    __nv_bfloat16 h0 = __float2bfloat16(f0), h1 = __float2bfloat16(f1);
    __nv_bfloat16 g0 = __float2bfloat16(f0 - __bfloat162float(h0));
    __nv_bfloat16 g1 = __float2bfloat16(f1 - __bfloat162float(h1));
    hi = (u32)__bfloat16_as_ushort(h0) | ((u32)__bfloat16_as_ushort(h1) << 16);
    lo = (u32)__bfloat16_as_ushort(g0) | ((u32)__bfloat16_as_ushort(g1) << 16);
}
__device__ __forceinline__ void bfsplit1(float f, __nv_bfloat16& h, __nv_bfloat16& l) {
    h = __float2bfloat16(f);
    l = __float2bfloat16(f - __bfloat162float(h));
}

// ---------------- cp.async -------------------------------------------------------
__device__ __forceinline__ void cp16s(u32 dst, const void* src) {
    asm volatile("cp.async.ca.shared.global [%0], [%1], 16;" :: "r"(dst), "l"(src));
}
#define CP_COMMIT() asm volatile("cp.async.commit_group;")
#define CP_WAIT0()  asm volatile("cp.async.wait_group 0;")
#define CP_WAIT1()  asm volatile("cp.async.wait_group 1;")

__device__ __forceinline__ u32 smem_u32(const void* p) {
    u32 a;
    asm("{ .reg .u64 t; cvta.to.shared.u64 t, %1; cvt.u32.u64 %0, t; }" : "=r"(a) : "l"(p));
    return a;
}

// ---------------- HMMA m16n8k16 bf16 + ldmatrix -----------------------------------
__device__ __forceinline__ void mma_bf16(float* d, const u32* a, const u32* b) {
    asm volatile(
        "mma.sync.aligned.m16n8k16.row.col.f32.bf16.bf16.f32 "
        "{%0,%1,%2,%3}, {%4,%5,%6,%7}, {%8,%9}, {%0,%1,%2,%3};"
        : "+f"(d[0]), "+f"(d[1]), "+f"(d[2]), "+f"(d[3])
        : "r"(a[0]), "r"(a[1]), "r"(a[2]), "r"(a[3]), "r"(b[0]), "r"(b[1]));
}
__device__ __forceinline__ void ldsm4(u32* r, u32 addr) {
    asm volatile("ldmatrix.sync.aligned.m8n8.x4.shared.b16 {%0,%1,%2,%3}, [%4];"
        : "=r"(r[0]), "=r"(r[1]), "=r"(r[2]), "=r"(r[3]) : "r"(addr));
}
__device__ __forceinline__ u32 ldsmA_addr(u32 base, int lane, int rowbase, int strideB) {
    int row = rowbase + (lane & 7) + (((lane >> 3) & 1) << 3);
    return base + (u32)(row * strideB) + (u32)((lane >> 4) << 4);
}
__device__ __forceinline__ u32 ldsmB_addr(u32 base, int lane, int strideB) {
    int row = (lane & 7) + ((lane >> 4) << 3);
    return base + (u32)(row * strideB) + (u32)(((lane >> 3) & 1) << 4);
}

// ================= shared HMMA GEMM core (k32 double-buffer, 2 CTAs/SM) ==========
// C[128x128] = A[128xK]*B[128xK]^T, 3-term split-bf16. 256 thr (8 warps).
// Per buffer: AH/AL/BH/BL each 128 rows x 80B (32 bf16 + pad) = 10240B -> 40960B.
#define HB_STRIDE 40960
#define GSM_SGL   81920

__device__ __forceinline__ void hmma_stage32(
    u32 base, int k0, int tid,
    const __nv_bfloat16* Ah, const __nv_bfloat16* Al, int lda,
    const __nv_bfloat16* Bh, const __nv_bfloat16* Bl, int ldb)
{
    #pragma unroll
    for (int q = 0; q < 2; q++) {
        int idx = (q << 8) + tid;            // 0..511
        int r = idx >> 2, ch = idx & 3;
        u32 off = (u32)(r * 80 + ch * 16);
        size_t sa = (size_t)r * lda + k0 + ch * 8;
        size_t sb = (size_t)r * ldb + k0 + ch * 8;
        cp16s(base + off,         Ah + sa);
        cp16s(base + 10240 + off, Al + sa);
        cp16s(base + 20480 + off, Bh + sb);
        cp16s(base + 30720 + off, Bl + sb);
    }
}

__device__ __forceinline__ void hmma_core(
    u32 smb,
    const __nv_bfloat16* Ah, const __nv_bfloat16* Al, int lda,
    const __nv_bfloat16* Bh, const __nv_bfloat16* Bl, int ldb,
    int kdim, float (&c)[16][4])
{
    const int tid = threadIdx.x;
    const int wid = tid >> 5, lane = tid & 31;

    #pragma unroll
    for (int n = 0; n < 16; n++)
        #pragma unroll
        for (int p = 0; p < 4; p++) c[n][p] = 0.0f;

    hmma_stage32(smb, 0, tid, Ah, Al, lda, Bh, Bl, ldb);
    CP_COMMIT();

    const int nsub = kdim >> 5;
    for (int kc = 0; kc < nsub; kc++) {
        if (kc + 1 < nsub) {
            hmma_stage32(smb + (u32)(((kc + 1) & 1) * HB_STRIDE), (kc + 1) << 5,
                         tid, Ah, Al, lda, Bh, Bl, ldb);
            CP_COMMIT();
            CP_WAIT1();
        } else {
            CP_WAIT0();
        }
        __syncthreads();

        const u32 bufb = smb + (u32)((kc & 1) * HB_STRIDE);
        const u32 aH = ldsmA_addr(bufb,         lane, wid << 4, 80);
        const u32 aL = ldsmA_addr(bufb + 10240, lane, wid << 4, 80);
        const u32 bH = ldsmB_addr(bufb + 20480, lane, 80);
        const u32 bL = ldsmB_addr(bufb + 30720, lane, 80);

        #pragma unroll
        for (int k = 0; k < 2; k++) {
            u32 ah[4], al[4];
            ldsm4(ah, aH + (k << 5));
            ldsm4(al, aL + (k << 5));
            #pragma unroll
            for (int np = 0; np < 8; np++) {
                u32 bh4[4], bl4[4];
                ldsm4(bh4, bH + (u32)(np * 16 * 80) + (k << 5));
                ldsm4(bl4, bL + (u32)(np * 16 * 80) + (k << 5));
                mma_bf16(c[np*2],   ah, &bh4[0]);
                mma_bf16(c[np*2],   al, &bh4[0]);
                mma_bf16(c[np*2],   ah, &bl4[0]);
                mma_bf16(c[np*2+1], ah, &bh4[2]);
                mma_bf16(c[np*2+1], al, &bh4[2]);
                mma_bf16(c[np*2+1], ah, &bl4[2]);
            }
        }
        __syncthreads();
    }
}

// ================= split prepasses =================================================
__global__ void __launch_bounds__(256) split_x_kernel(
    const float* __restrict__ x,
    __nv_bfloat16* __restrict__ xhi, __nv_bfloat16* __restrict__ xlo)
{
    int i = blockIdx.x * 256 + threadIdx.x;
    if (i < MROWS * DIMM / 2) {
        float2 f = *(const float2*)(x + 2 * (size_t)i);
        u32 h, l;
        bfsplit2(f.x, f.y, h, l);
        *(u32*)(xhi + 2 * (size_t)i) = h;
        *(u32*)(xlo + 2 * (size_t)i) = l;
    }
}

__global__ void __launch_bounds__(256) split_w_kernel(
    const float* __restrict__ Wq, const float* __restrict__ Wkv,
    const float* __restrict__ Wo,
    __nv_bfloat16* __restrict__ Wthi, __nv_bfloat16* __restrict__ Wtlo,
    __nv_bfloat16* __restrict__ WoThi, __nv_bfloat16* __restrict__ WoTlo)
{
    int idx = blockIdx.x * 256 + threadIdx.x;
    if (idx < 1536 * 256) {
        int c = idx >> 8, k = (idx & 255) << 1;
        float f0, f1;
        if (c < 512) { f0 = Wq[(size_t)k * 512 + c];  f1 = Wq[(size_t)(k+1) * 512 + c]; }
        else { f0 = Wkv[(size_t)k * 1024 + c - 512]; f1 = Wkv[(size_t)(k+1) * 1024 + c - 512]; }
        u32 h, l;
        bfsplit2(f0, f1, h, l);
        *(u32*)(Wthi + (size_t)c * 512 + k) = h;
        *(u32*)(Wtlo + (size_t)c * 512 + k) = l;
    } else if (idx < 1536 * 256 + 512 * 256) {
        int j = idx - 1536 * 256;
        int c = j >> 8, k = (j & 255) << 1;
        float f0 = Wo[(size_t)k * 512 + c], f1 = Wo[(size_t)(k+1) * 512 + c];
        u32 h, l;
        bfsplit2(f0, f1, h, l);
        *(u32*)(WoThi + (size_t)c * 512 + k) = h;
        *(u32*)(WoTlo + (size_t)c * 512 + k) = l;
    }
}

__global__ void __launch_bounds__(256) split_rel_kernel(
    const float* __restrict__ rel,
    __nv_bfloat16* __restrict__ relhi, __nv_bfloat16* __restrict__ rello)
{
    int idx = blockIdx.x * 256 + threadIdx.x;
    if (idx < 1152 * 32) {
        int t = idx >> 5, dp = (idx & 31) << 1;
        float f0 = 0.0f, f1 = 0.0f;
        if (t < TVALS) {
            f0 = rel[(size_t)t * DHEAD + dp];
            f1 = rel[(size_t)t * DHEAD + dp + 1];
        }
        u32 h, l;
        bfsplit2(f0, f1, h, l);
        *(u32*)(relhi + (size_t)t * DHEAD + dp) = h;
        *(u32*)(rello + (size_t)t * DHEAD + dp) = l;
    }
}

// ================= kernel 1: QKV projection (HMMA) =================================
__global__ void __launch_bounds__(256, 2) qkv_hmma_kernel(
    const __nv_bfloat16* __restrict__ xhi, const __nv_bfloat16* __restrict__ xlo,
    const __nv_bfloat16* __restrict__ Wthi, const __nv_bfloat16* __restrict__ Wtlo,
    __nv_bfloat16* __restrict__ Qhi, __nv_bfloat16* __restrict__ Qlo,
    __nv_bfloat16* __restrict__ Khi, __nv_bfloat16* __restrict__ Klo,
    __nv_bfloat16* __restrict__ Vhi, __nv_bfloat16* __restrict__ Vlo)
{
    extern __shared__ char smc[];
    const u32 smb = smem_u32(smc);
    const int m0 = blockIdx.x << 7;
    const int c0 = blockIdx.y << 7;

    float c[16][4];
    hmma_core(smb, xhi + (size_t)m0 * DIMM, xlo + (size_t)m0 * DIMM, DIMM,
              Wthi + (size_t)c0 * DIMM, Wtlo + (size_t)c0 * DIMM, DIMM, DIMM, c);

    const int tid = threadIdx.x, wid = tid >> 5, lane = tid & 31;
    const int ln4 = lane >> 2, lm4 = lane & 3;
    const int b = m0 >> 11;
    const int ns0 = (m0 & 2047) + (wid << 4) + ln4;

    if (c0 < 1024) {
        const float sc = (c0 < 512) ? SCALE_F : 1.0f;
        __nv_bfloat16* Dh = (c0 < 512) ? Qhi : Khi;
        __nv_bfloat16* Dl = (c0 < 512) ? Qlo : Klo;
        #pragma unroll
        for (int n = 0; n < 16; n++) {
            int col = (c0 & 511) + n * 8 + (lm4 << 1);
            int head = col >> 6, dl = col & 63;
            size_t base0 = (((size_t)(b * HEADS + head)) * NSEQ + ns0) * DHEAD + dl;
            size_t base1 = base0 + 8 * DHEAD;
            u32 h, l;
            bfsplit2(c[n][0] * sc, c[n][1] * sc, h, l);
            *(u32*)(Dh + base0) = h; *(u32*)(Dl + base0) = l;
            bfsplit2(c[n][2] * sc, c[n][3] * sc, h, l);
            *(u32*)(Dh + base1) = h; *(u32*)(Dl + base1) = l;
        }
    } else {
        #pragma unroll
        for (int n = 0; n < 16; n++) {
            int col = (c0 - 1024) + n * 8 + (lm4 << 1);
            int head = col >> 6, d0 = col & 63;
            size_t rowbase = ((size_t)(b * HEADS + head) * DHEAD + d0) * NSEQ;
            #pragma unroll
            for (int e = 0; e < 2; e++) {
                __nv_bfloat16 h, l;
                bfsplit1(c[n][e], h, l);
                Vhi[rowbase + (size_t)e * NSEQ + ns0] = h;
                Vlo[rowbase + (size_t)e * NSEQ + ns0] = l;
                bfsplit1(c[n][2 + e], h, l);
                Vhi[rowbase + (size_t)e * NSEQ + ns0 + 8] = h;
                Vlo[rowbase + (size_t)e * NSEQ + ns0 + 8] = l;
            }
        }
    }
}

// ================= kernel 2: P = Qscaled @ rel^T (HMMA, K=64) =======================
__global__ void __launch_bounds__(256, 2) p_hmma_kernel(
    const __nv_bfloat16* __restrict__ Qhi, const __nv_bfloat16* __restrict__ Qlo,
    const __nv_bfloat16* __restrict__ relhi, const __nv_bfloat16* __restrict__ rello,
    float* __restrict__ P)
{
    extern __shared__ char smc[];
    const u32 smb = smem_u32(smc);
    const int m0 = blockIdx.x << 7;
    const int t0 = blockIdx.y << 7;

    float c[16][4];
    hmma_core(smb, Qhi + (size_t)m0 * DHEAD, Qlo + (size_t)m0 * DHEAD, DHEAD,
              relhi + (size_t)t0 * DHEAD, rello + (size_t)t0 * DHEAD, DHEAD, DHEAD, c);

    const int tid = threadIdx.x, wid = tid >> 5, lane = tid & 31;
    const int ln4 = lane >> 2, lm4 = lane & 3;
    const size_t r0 = m0 + (wid << 4) + ln4;

    #pragma unroll
    for (int n = 0; n < 16; n++) {
        int col = t0 + n * 8 + (lm4 << 1);
        if (col + 1 < TVALS) {
            *(float2*)(P + r0 * PLD + col) = make_float2(c[n][0], c[n][1]);
            *(float2*)(P + (r0 + 8) * PLD + col) = make_float2(c[n][2], c[n][3]);
        } else if (col < TVALS) {
            P[r0 * PLD + col] = c[n][0];
            P[(r0 + 8) * PLD + col] = c[n][2];
        }
    }
}

// ================= kernel 3: HMMA flash attention (phase-split prefetch) ============
#define FQH 0
#define FQL 18432
#define FKH 36864
#define FKL 55296
#define FVH 73728
#define FVL 91136
#define FSM_TOTAL 108544

__device__ __forceinline__ void stage_k_tile(
    u32 smb, int j0, int tid,
    const __nv_bfloat16* Kh, const __nv_bfloat16* Kl)
{
    #pragma unroll
    for (int q = 0; q < 4; q++) {
        int idx = (q << 8) + tid;
        int r = idx >> 3, ch = idx & 7;
        u32 off = (u32)(r * 144 + ch * 16);
        size_t src = (size_t)(j0 + r) * DHEAD + ch * 8;
        cp16s(smb + FKH + off, Kh + src);
        cp16s(smb + FKL + off, Kl + src);
    }
}
__device__ __forceinline__ void stage_v_tile(
    u32 smb, int j0, int tid,
    const __nv_bfloat16* Vh, const __nv_bfloat16* Vl)
{
    #pragma unroll
    for (int q = 0; q < 4; q++) {
        int idx = (q << 8) + tid;
        int d = idx >> 4, ch = idx & 15;
        u32 off = (u32)(d * 272 + ch * 16);
        size_t src = (size_t)d * NSEQ + j0 + ch * 8;
        cp16s(smb + FVH + off, Vh + src);
        cp16s(smb + FVL + off, Vl + src);
    }
}

__global__ void __launch_bounds__(256, 2) flash_kernel(
    const __nv_bfloat16* __restrict__ Qhi, const __nv_bfloat16* __restrict__ Qlo,
    const __nv_bfloat16* __restrict__ Khi, const __nv_bfloat16* __restrict__ Klo,
    const __nv_bfloat16* __restrict__ Vhi, const __nv_bfloat16* __restrict__ Vlo,
    const float* __restrict__ P,
    __nv_bfloat16* __restrict__ Ohi, __nv_bfloat16* __restrict__ Olo)
{
    extern __shared__ char smc[];
    const u32 smb = smem_u32(smc);

    const int tid  = threadIdx.x;
    const int wid  = tid >> 5, lane = tid & 31;
    const int ln4  = lane >> 2;
    const int lm4  = lane & 3;
    const int bh   = blockIdx.y, n0 = blockIdx.x << 7;
    const int b    = bh >> 3, head = bh & 7;

    const __nv_bfloat16* Qhg = Qhi + ((size_t)bh * NSEQ + n0) * DHEAD;
    const __nv_bfloat16* Qlg = Qlo + ((size_t)bh * NSEQ + n0) * DHEAD;
    const __nv_bfloat16* Khg = Khi + (size_t)bh * NSEQ * DHEAD;
    const __nv_bfloat16* Klg = Klo + (size_t)bh * NSEQ * DHEAD;
    const __nv_bfloat16* Vhg = Vhi + (size_t)bh * DHEAD * NSEQ;
    const __nv_bfloat16* Vlg = Vlo + (size_t)bh * DHEAD * NSEQ;

    const u32 qH = ldsmA_addr(smb + FQH, lane, wid << 4, 144);
    const u32 qL = ldsmA_addr(smb + FQL, lane, wid << 4, 144);
    const u32 kH = ldsmB_addr(smb + FKH, lane, 144);
    const u32 kL = ldsmB_addr(smb + FKL, lane, 144);
    const u32 vH = ldsmB_addr(smb + FVH, lane, 272);
    const u32 vL = ldsmB_addr(smb + FVL, lane, 272);

    // prologue: group1 = Q + K0, group2 = V0
    #pragma unroll
    for (int q = 0; q < 4; q++) {
        int idx = (q << 8) + tid;
        int r = idx >> 3, ch = idx & 7;
        u32 off = (u32)(r * 144 + ch * 16);
        size_t src = (size_t)r * DHEAD + ch * 8;
        cp16s(smb + FQH + off, Qhg + src);
        cp16s(smb + FQL + off, Qlg + src);
    }
    stage_k_tile(smb, 0, tid, Khg, Klg);
    CP_COMMIT();
    stage_v_tile(smb, 0, tid, Vhg, Vlg);
    CP_COMMIT();

    const int r0 = (wid << 4) + ln4;
    const float* prow0 = P + ((size_t)bh * NSEQ + n0 + r0) * PLD;
    const float* prow1 = prow0 + 8 * PLD;

    float o[8][4];
    #pragma unroll
    for (int n = 0; n < 8; n++)
        #pragma unroll
        for (int p = 0; p < 4; p++) o[n][p] = 0.0f;
    float lsum0 = 0.0f, lsum1 = 0.0f;

    for (int jt = 0; jt < 16; jt++) {
        const int j0 = jt << 7;

        CP_WAIT1();                            // Q + K(jt) ready (V group may lag)
        __syncthreads();

        #pragma unroll
        for (int half = 0; half < 2; half++) {
            // ---- S half = Q K^T : 16 rows x 64 cols, 3-term split -------------
            float c[8][4];
            #pragma unroll
            for (int n = 0; n < 8; n++)
                #pragma unroll
                for (int p = 0; p < 4; p++) c[n][p] = 0.0f;

            #pragma unroll
            for (int k = 0; k < 4; k++) {
                u32 qh4[4], ql4[4];
                ldsm4(qh4, qH + (k << 5));
                ldsm4(ql4, qL + (k << 5));
                #pragma unroll
                for (int np = 0; np < 4; np++) {
                    u32 rowoff = (u32)((half * 64 + np * 16) * 144);
                    u32 bh4[4], bl4[4];
                    ldsm4(bh4, kH + rowoff + (k << 5));
                    ldsm4(bl4, kL + rowoff + (k << 5));
                    mma_bf16(c[np*2],   qh4, &bh4[0]);
                    mma_bf16(c[np*2],   ql4, &bh4[0]);
                    mma_bf16(c[np*2],   qh4, &bl4[0]);
                    mma_bf16(c[np*2+1], qh4, &bh4[2]);
                    mma_bf16(c[np*2+1], ql4, &bh4[2]);
                    mma_bf16(c[np*2+1], qh4, &bl4[2]);
                }
            }

            if (half == 1) {                   // K fully consumed -> prefetch next K
                __syncthreads();
                if (jt + 1 < 16) {
                    stage_k_tile(smb, j0 + 128, tid, Khg, Klg);
                    CP_COMMIT();
                }
            }

            // ---- bias + exp (no max shift; scores bounded) ---------------------
            #pragma unroll
            for (int n = 0; n < 8; n++) {
                const int jb = j0 + half * 64 + n * 8 + (lm4 << 1);
                int t0 = (n0 + r0) - jb + 512;
                int ta = t0 < 0 ? 0 : (t0 > 1024 ? 1024 : t0);
                int t1 = t0 - 1;
                int tb = t1 < 0 ? 0 : (t1 > 1024 ? 1024 : t1);
                int t2 = t0 + 8;
                int tc = t2 < 0 ? 0 : (t2 > 1024 ? 1024 : t2);
                int t3 = t0 + 7;
                int td = t3 < 0 ? 0 : (t3 > 1024 ? 1024 : t3);
                float p0 = __expf(c[n][0] + prow0[ta]);
                float p1 = __expf(c[n][1] + prow0[tb]);
                float p2 = __expf(c[n][2] + prow1[tc]);
                float p3 = __expf(c[n][3] + prow1[td]);
                lsum0 += p0 + p1;
                lsum1 += p2 + p3;
                c[n][0] = p0; c[n][1] = p1; c[n][2] = p2; c[n][3] = p3;
            }

            if (half == 0) {                   // V(jt) must be resident before PV
                CP_WAIT0();
                __syncthreads();
            }

            // ---- pack P frags (C-frag -> A-frag reuse) -------------------------
            u32 Ah[4][4], Al[4][4];
            #pragma unroll
            for (int k = 0; k < 4; k++) {
                bfsplit2(c[2*k][0],   c[2*k][1],   Ah[k][0], Al[k][0]);
                bfsplit2(c[2*k][2],   c[2*k][3],   Ah[k][1], Al[k][1]);
                bfsplit2(c[2*k+1][0], c[2*k+1][1], Ah[k][2], Al[k][2]);
                bfsplit2(c[2*k+1][2], c[2*k+1][3], Ah[k][3], Al[k][3]);
            }

            // ---- O += P(half) V(half k rows) -----------------------------------
            #pragma unroll
            for (int k = 0; k < 4; k++) {
                const int kk = half * 4 + k;
                #pragma unroll
                for (int np = 0; np < 4; np++) {
                    u32 rowoff = (u32)(np * 16 * 272);
                    u32 vh4[4], vl4[4];
                    ldsm4(vh4, vH + rowoff + (kk << 5));
                    ldsm4(vl4, vL + rowoff + (kk << 5));
                    mma_bf16(o[np*2],   Ah[k], &vh4[0]);
                    mma_bf16(o[np*2],   Al[k], &vh4[0]);
                    mma_bf16(o[np*2],   Ah[k], &vl4[0]);
                    mma_bf16(o[np*2+1], Ah[k], &vh4[2]);
                    mma_bf16(o[np*2+1], Al[k], &vh4[2]);
                    mma_bf16(o[np*2+1], Ah[k], &vl4[2]);
                }
            }
        }

        __syncthreads();                       // V fully consumed -> prefetch next V
        if (jt + 1 < 16) {
            stage_v_tile(smb, j0 + 128, tid, Vhg, Vlg);
            CP_COMMIT();
        }
    }

    lsum0 += __shfl_xor_sync(0xffffffffu, lsum0, 1);
    lsum0 += __shfl_xor_sync(0xffffffffu, lsum0, 2);
    lsum1 += __shfl_xor_sync(0xffffffffu, lsum1, 1);
    lsum1 += __shfl_xor_sync(0xffffffffu, lsum1, 2);
    const float inv0 = 1.0f / lsum0;
    const float inv1 = 1.0f / lsum1;

    size_t ob0 = ((size_t)(b * NSEQ + n0 + r0)) * DIMM + (head << 6) + (lm4 << 1);
    size_t ob1 = ob0 + 8 * DIMM;
    #pragma unroll
    for (int n = 0; n < 8; n++) {
        u32 h, l;
        bfsplit2(o[n][0] * inv0, o[n][1] * inv0, h, l);
        *(u32*)(Ohi + ob0 + n * 8) = h;
        *(u32*)(Olo + ob0 + n * 8) = l;
        bfsplit2(o[n][2] * inv1, o[n][3] * inv1, h, l);
        *(u32*)(Ohi + ob1 + n * 8) = h;
        *(u32*)(Olo + ob1 + n * 8) = l;
    }
}

// ================= kernel 4: output projection (HMMA) ==============================
__global__ void __launch_bounds__(256, 2) out_hmma_kernel(
    const __nv_bfloat16* __restrict__ Ohi, const __nv_bfloat16* __restrict__ Olo,
    const __nv_bfloat16* __restrict__ WoThi, const __nv_bfloat16* __restrict__ WoTlo,
    const float* __restrict__ bo, float* __restrict__ out)
{
    extern __shared__ char smc[];
    const u32 smb = smem_u32(smc);
    const int m0 = blockIdx.x << 7;
    const int c0 = blockIdx.y << 7;

    float c[16][4];
    hmma_core(smb, Ohi + (size_t)m0 * DIMM, Olo + (size_t)m0 * DIMM, DIMM,
              WoThi + (size_t)c0 * DIMM, WoTlo + (size_t)c0 * DIMM, DIMM, DIMM, c);

    const int tid = threadIdx.x, wid = tid >> 5, lane = tid & 31;
    const int ln4 = lane >> 2, lm4 = lane & 3;
    const size_t r0 = m0 + (wid << 4) + ln4;

    #pragma unroll
    for (int n = 0; n < 16; n++) {
        int col = c0 + n * 8 + (lm4 << 1);
        float2 bb = *(const float2*)(bo + col);
        *(float2*)(out + r0 * DIMM + col) = make_float2(c[n][0] + bb.x, c[n][1] + bb.y);
        *(float2*)(out + (r0 + 8) * DIMM + col) = make_float2(c[n][2] + bb.x, c[n][3] + bb.y);
    }
}

// ================= launch ==========================================================
extern "C" void kernel_launch(void* const* d_in, const int* in_sizes, int n_in,
                              void* d_out, int out_size)
{
    const float* x   = (const float*)d_in[0];
    const float* Wq  = (const float*)d_in[1];
    const float* Wkv = (const float*)d_in[2];
    const float* Wo  = (const float*)d_in[3];
    const float* bo  = (const float*)d_in[4];
    const float* rel = (const float*)d_in[5];
    float* out = (float*)d_out;

    __nv_bfloat16 *xh, *xl, *wth, *wtl, *woh, *wol, *rh, *rl;
    __nv_bfloat16 *qh, *ql, *kh, *kl, *vh, *vl, *oh, *ol;
    float *Pp;
    cudaGetSymbolAddress((void**)&xh,  g_xhi);
    cudaGetSymbolAddress((void**)&xl,  g_xlo);
    cudaGetSymbolAddress((void**)&wth, g_Wthi);
    cudaGetSymbolAddress((void**)&wtl, g_Wtlo);
    cudaGetSymbolAddress((void**)&woh, g_WoThi);
    cudaGetSymbolAddress((void**)&wol, g_WoTlo);
    cudaGetSymbolAddress((void**)&rh,  g_relhi);
    cudaGetSymbolAddress((void**)&rl,  g_rello);
    cudaGetSymbolAddress((void**)&qh,  g_Qhi);
    cudaGetSymbolAddress((void**)&ql,  g_Qlo);
    cudaGetSymbolAddress((void**)&kh,  g_Khi);
    cudaGetSymbolAddress((void**)&kl,  g_Klo);
    cudaGetSymbolAddress((void**)&vh,  g_Vhi);
    cudaGetSymbolAddress((void**)&vl,  g_Vlo);
    cudaGetSymbolAddress((void**)&oh,  g_Ohi);
    cudaGetSymbolAddress((void**)&ol,  g_Olo);
    cudaGetSymbolAddress((void**)&Pp,  g_P);

    cudaFuncSetAttribute(qkv_hmma_kernel,
                         cudaFuncAttributeMaxDynamicSharedMemorySize, GSM_SGL);
    cudaFuncSetAttribute(p_hmma_kernel,
                         cudaFuncAttributeMaxDynamicSharedMemorySize, GSM_SGL);
    cudaFuncSetAttribute(out_hmma_kernel,
                         cudaFuncAttributeMaxDynamicSharedMemorySize, GSM_SGL);
    cudaFuncSetAttribute(flash_kernel,
                         cudaFuncAttributeMaxDynamicSharedMemorySize, FSM_TOTAL);

    split_x_kernel<<<MROWS * DIMM / 512, 256>>>(x, xh, xl);
    split_w_kernel<<<2048, 256>>>(Wq, Wkv, Wo, wth, wtl, woh, wol);
    split_rel_kernel<<<144, 256>>>(rel, rh, rl);

    qkv_hmma_kernel<<<dim3(32, 12), 256, GSM_SGL>>>(xh, xl, wth, wtl,
                                                    qh, ql, kh, kl, vh, vl);
    p_hmma_kernel<<<dim3(256, 9), 256, GSM_SGL>>>(qh, ql, rh, rl, Pp);
    flash_kernel<<<dim3(16, 16), 256, FSM_TOTAL>>>(qh, ql, kh, kl, vh, vl, Pp, oh, ol);
    out_hmma_kernel<<<dim3(32, 4), 256, GSM_SGL>>>(oh, ol, woh, wol, bo, out);
}